// round 8
// baseline (speedup 1.0000x reference)
#include <cuda_runtime.h>
#include <math.h>

// ---------------- problem constants ----------------
#define BB   8
#define TT   2048
#define DD   768
#define VQn  64
#define KK   4096
#define HID  1024
#define NMID 4
#define BT   (BB*TT)          // 16384
#define EPS_N  1e-6f
#define EPS_BN 1e-5f

typedef unsigned long long u64;

// ---------------- f32x2 packed-FMA primitives ----------------
__device__ __forceinline__ void ffma2(u64& d, u64 a, u64 b) {
    asm("fma.rn.f32x2 %0, %1, %2, %0;" : "+l"(d) : "l"(a), "l"(b));
}
__device__ __forceinline__ float2 u2f(u64 v) {
    float2 r; asm("mov.b64 {%0, %1}, %2;" : "=f"(r.x), "=f"(r.y) : "l"(v)); return r;
}
__device__ __forceinline__ u64 fdup(float x) {
    u64 r; asm("mov.b64 %0, {%1, %1};" : "=l"(r) : "f"(x)); return r;
}

// ---------------- device scratch ----------------
__device__ float g_bufA[KK*HID];        // 16 MB
__device__ float g_bufB[KK*HID];        // 16 MB
__device__ float g_hT[BT*DD];           // 50 MB   h_in transposed to [B,T,D]
__device__ float g_h[BT*VQn];           // 4 MB
__device__ float g_hsq[BT];
__device__ float g_embed[KK*VQn];
__device__ float g_esq[KK];
__device__ float g_einv[KK*DD];         // 12.6 MB
__device__ int   g_code[BT];
__device__ float g_psum[32*HID];
__device__ float g_psumsq[32*HID];
__device__ float g_bns[HID];
__device__ float g_bnt[HID];

// ---------------- layer 0: bits @ W_in^T + b ----------------
__global__ void k_layer0(const float* __restrict__ w, const float* __restrict__ b,
                         float* __restrict__ Y) {
    int idx = blockIdx.x*256 + threadIdx.x;
    int k = idx >> 10, j = idx & 1023;
    float acc = 0.f;
    #pragma unroll
    for (int l = 0; l < 12; l++)
        if (k & (1 << (11-l))) acc += w[j*12 + l];
    Y[idx] = acc + b[j];
}

// ---------------- BN stats for layer0 output (deterministic 2-stage) ----------------
__global__ void k_bn_part(const float* __restrict__ Y,
                          float* __restrict__ ps, float* __restrict__ pss) {
    int j  = blockIdx.x*256 + threadIdx.x;
    int r0 = blockIdx.y * 128;
    float s = 0.f, ss = 0.f;
    for (int r = 0; r < 128; r++) {
        float v = Y[(r0+r)*HID + j];
        s += v; ss += v*v;
    }
    ps [blockIdx.y*HID + j] = s;
    pss[blockIdx.y*HID + j] = ss;
}
__global__ void k_bn_final(const float* __restrict__ ps, const float* __restrict__ pss,
                           const float* __restrict__ gamma, const float* __restrict__ beta,
                           float* __restrict__ so, float* __restrict__ to) {
    int j = blockIdx.x*256 + threadIdx.x;
    float s = 0.f, q = 0.f;
    #pragma unroll
    for (int p = 0; p < 32; p++) { s += ps[p*HID + j]; q += pss[p*HID + j]; }
    float m   = s * (1.0f/KK);
    float var = q * (1.0f/KK) - m*m;
    float inv = 1.0f / sqrtf(var + EPS_BN);
    float sc  = gamma[j] * inv;
    so[j] = sc;
    to[j] = beta[j] - m*sc;
}

// ---------------- fused NT SGEMM (FFMA2): C[M,N] = act(A)[M,K] * B[N,K]^T + bias ----------------
template<int BM,int BN,int BK,int TM,int TN,bool BNIN,bool STATS>
__global__ void __launch_bounds__(256, 2)
k_gemm(const float* __restrict__ A,
       const float* __restrict__ bns, const float* __restrict__ bnt,
       const float* __restrict__ B, const float* __restrict__ bias,
       float* __restrict__ C,
       float* __restrict__ ps, float* __restrict__ pss,
       int M, int N, int Kd) {
    constexpr int THREADS = (BM/TM)*(BN/TN);     // 256
    constexpr int ASTR = BM+4, BSTR = BN+4;
    constexpr int MAINF = BK*ASTR + BK*BSTR;
    constexpr int STATF = 2*(BM/TM)*BN;
    constexpr int SMEMF = (MAINF > STATF) ? MAINF : STATF;
    __shared__ float sm[SMEMF];
    float (*As)[ASTR] = (float(*)[ASTR])sm;
    float (*Bs)[BSTR] = (float(*)[BSTR])(sm + BK*ASTR);

    int tid = threadIdx.x;
    int tx = tid % (BN/TN);
    int ty = tid / (BN/TN);
    int m0 = blockIdx.y*BM, n0 = blockIdx.x*BN;

    u64 acc2[TM/2][TN];
    #pragma unroll
    for (int i = 0; i < TM/2; i++)
        #pragma unroll
        for (int j = 0; j < TN; j++) acc2[i][j] = 0ULL;

    constexpr int A_PER = (BM*BK/4)/THREADS;
    constexpr int B_PER = (BN*BK/4)/THREADS;

    for (int k0 = 0; k0 < Kd; k0 += BK) {
        #pragma unroll
        for (int i = 0; i < A_PER; i++) {
            int f = tid + i*THREADS;
            int m = f / (BK/4);
            int kc = (f % (BK/4)) * 4;
            float4 v = *(const float4*)&A[(size_t)(m0+m)*Kd + k0 + kc];
            if (BNIN) {
                float4 s4 = *(const float4*)&bns[k0 + kc];
                float4 t4 = *(const float4*)&bnt[k0 + kc];
                v.x = fmaxf(fmaf(v.x, s4.x, t4.x), 0.f);
                v.y = fmaxf(fmaf(v.y, s4.y, t4.y), 0.f);
                v.z = fmaxf(fmaf(v.z, s4.z, t4.z), 0.f);
                v.w = fmaxf(fmaf(v.w, s4.w, t4.w), 0.f);
            }
            As[kc+0][m]=v.x; As[kc+1][m]=v.y; As[kc+2][m]=v.z; As[kc+3][m]=v.w;
        }
        #pragma unroll
        for (int i = 0; i < B_PER; i++) {
            int f = tid + i*THREADS;
            int n = f / (BK/4);
            int kc = (f % (BK/4)) * 4;
            float4 v = *(const float4*)&B[(size_t)(n0+n)*Kd + k0 + kc];
            Bs[kc+0][n]=v.x; Bs[kc+1][n]=v.y; Bs[kc+2][n]=v.z; Bs[kc+3][n]=v.w;
        }
        __syncthreads();
        #pragma unroll
        for (int k = 0; k < BK; k++) {
            ulonglong2 av0 = *(const ulonglong2*)&As[k][ty*TM];
            ulonglong2 av1 = *(const ulonglong2*)&As[k][ty*TM + 4];
            u64 ap[4] = {av0.x, av0.y, av1.x, av1.y};
            u64 bd[TN];
            {
                float4 b0 = *(const float4*)&Bs[k][tx*TN];
                bd[0]=fdup(b0.x); bd[1]=fdup(b0.y); bd[2]=fdup(b0.z); bd[3]=fdup(b0.w);
                if (TN == 8) {
                    float4 b1 = *(const float4*)&Bs[k][tx*TN + 4];
                    bd[4]=fdup(b1.x); bd[5]=fdup(b1.y); bd[6]=fdup(b1.z); bd[7]=fdup(b1.w);
                }
            }
            #pragma unroll
            for (int i2 = 0; i2 < TM/2; i2++)
                #pragma unroll
                for (int j = 0; j < TN; j++)
                    ffma2(acc2[i2][j], ap[i2], bd[j]);
        }
        __syncthreads();
    }

    // epilogue: unpack + bias
    float accf[TM][TN];
    #pragma unroll
    for (int i2 = 0; i2 < TM/2; i2++)
        #pragma unroll
        for (int j = 0; j < TN; j++) {
            float2 p = u2f(acc2[i2][j]);
            float bj = bias[n0 + tx*TN + j];
            accf[2*i2][j]   = p.x + bj;
            accf[2*i2+1][j] = p.y + bj;
        }
    #pragma unroll
    for (int i = 0; i < TM; i++) {
        int m = m0 + ty*TM + i;
        #pragma unroll
        for (int jj = 0; jj < TN/4; jj++) {
            int n = n0 + tx*TN + jj*4;
            float4 v;
            v.x = accf[i][jj*4+0]; v.y = accf[i][jj*4+1];
            v.z = accf[i][jj*4+2]; v.w = accf[i][jj*4+3];
            *(float4*)&C[(size_t)m*N + n] = v;
        }
    }
    if (STATS) {
        __syncthreads();
        float* shS = sm;
        float* shQ = sm + (BM/TM)*BN;
        #pragma unroll
        for (int j = 0; j < TN; j++) {
            float s = 0.f, q = 0.f;
            #pragma unroll
            for (int i = 0; i < TM; i++) { float v = accf[i][j]; s += v; q += v*v; }
            shS[ty*BN + tx*TN + j] = s;
            shQ[ty*BN + tx*TN + j] = q;
        }
        __syncthreads();
        if (tid < BN) {
            float s = 0.f, q = 0.f;
            #pragma unroll
            for (int p = 0; p < BM/TM; p++) { s += shS[p*BN + tid]; q += shQ[p*BN + tid]; }
            ps [blockIdx.y*N + n0 + tid] = s;
            pss[blockIdx.y*N + n0 + tid] = q;
        }
    }
}

// ---------------- row L2-normalize (64-wide rows), post-norm sumsq ----------------
__global__ void k_l2norm(float* __restrict__ X, float* __restrict__ sq, int M) {
    int row  = blockIdx.x * 8 + (threadIdx.x >> 5);
    int lane = threadIdx.x & 31;
    if (row >= M) return;
    float* p = X + (size_t)row*64;
    float v0 = p[lane], v1 = p[lane+32];
    float s = v0*v0 + v1*v1;
    #pragma unroll
    for (int o = 16; o; o >>= 1) s += __shfl_xor_sync(0xFFFFFFFFu, s, o);
    float inv = 1.0f / (sqrtf(s) + EPS_N);
    v0 *= inv; v1 *= inv;
    p[lane] = v0; p[lane+32] = v1;
    float s2 = v0*v0 + v1*v1;
    #pragma unroll
    for (int o = 16; o; o >>= 1) s2 += __shfl_xor_sync(0xFFFFFFFFu, s2, o);
    if (lane == 0) sq[row] = s2;
}

// ---------------- transpose h_in [B,D,T] -> [B,T,D] ----------------
__global__ void k_transpose(const float* __restrict__ in, float* __restrict__ out) {
    __shared__ float tile[32][33];
    int b  = blockIdx.z;
    int t0 = blockIdx.x*32, d0 = blockIdx.y*32;
    int x = threadIdx.x, y = threadIdx.y;   // (32,8)
    #pragma unroll
    for (int i = 0; i < 32; i += 8)
        tile[y+i][x] = in[(size_t)b*DD*TT + (size_t)(d0+y+i)*TT + t0 + x];
    __syncthreads();
    #pragma unroll
    for (int i = 0; i < 32; i += 8)
        out[(size_t)b*TT*DD + (size_t)(t0+y+i)*DD + d0 + x] = tile[x][y+i];
}

// ---------------- fused distance + argmin (256 threads; per-element order identical) --------------
__global__ void __launch_bounds__(256)
k_argmin(const float* __restrict__ h, const float* __restrict__ hsq,
         const float* __restrict__ embed, const float* __restrict__ esq,
         int* __restrict__ code) {
    extern __shared__ float dsm[];
    float (*Hst)[132] = (float(*)[132])dsm;            // [64 k][128 rows + pad]
    float (*Est)[68]  = (float(*)[68])(dsm + 64*132);  // [64 k][64 codes + pad]
    float* Eq = dsm + 64*132 + 64*68;                  // [64]
    int tid = threadIdx.x;
    int tx = tid & 7;          // code group (8 x 8 codes)
    int ty = tid >> 3;         // row group  (32 x 4 rows)
    int r0 = blockIdx.x * 128;

    // load H tile [128 rows][64 k]
    #pragma unroll
    for (int i = 0; i < 8; i++) {
        int f = tid + i*256;
        int r = f >> 4;
        int kc = (f & 15) * 4;
        float4 v = *(const float4*)&h[(size_t)(r0+r)*64 + kc];
        Hst[kc+0][r]=v.x; Hst[kc+1][r]=v.y; Hst[kc+2][r]=v.z; Hst[kc+3][r]=v.w;
    }
    float hq[4];
    #pragma unroll
    for (int i = 0; i < 4; i++) hq[i] = hsq[r0 + ty*4 + i];
    float best[4]; int bidx[4];
    #pragma unroll
    for (int i = 0; i < 4; i++) { best[i] = 3.4e38f; bidx[i] = 0; }

    for (int c0 = 0; c0 < KK; c0 += 64) {
        #pragma unroll
        for (int i = 0; i < 4; i++) {
            int f = tid + i*256;
            int c = f >> 4;
            int kc = (f & 15) * 4;
            float4 v = *(const float4*)&embed[(size_t)(c0+c)*64 + kc];
            Est[kc+0][c]=v.x; Est[kc+1][c]=v.y; Est[kc+2][c]=v.z; Est[kc+3][c]=v.w;
        }
        if (tid < 64) Eq[tid] = esq[c0 + tid];
        __syncthreads();
        u64 acc2[2][8];
        #pragma unroll
        for (int i = 0; i < 2; i++)
            #pragma unroll
            for (int j = 0; j < 8; j++) acc2[i][j] = 0ULL;
        #pragma unroll 16
        for (int k = 0; k < 64; k++) {
            ulonglong2 a0 = *(const ulonglong2*)&Hst[k][ty*4];
            u64 ap[2] = {a0.x, a0.y};
            float4 b0 = *(const float4*)&Est[k][tx*8];
            float4 b1 = *(const float4*)&Est[k][tx*8 + 4];
            u64 bd[8] = {fdup(b0.x), fdup(b0.y), fdup(b0.z), fdup(b0.w),
                         fdup(b1.x), fdup(b1.y), fdup(b1.z), fdup(b1.w)};
            #pragma unroll
            for (int i2 = 0; i2 < 2; i2++)
                #pragma unroll
                for (int j = 0; j < 8; j++)
                    ffma2(acc2[i2][j], ap[i2], bd[j]);
        }
        #pragma unroll
        for (int i2 = 0; i2 < 2; i2++)
            #pragma unroll
            for (int j = 0; j < 8; j++) {
                float2 p = u2f(acc2[i2][j]);
                int cc = c0 + tx*8 + j;
                float eq = Eq[tx*8 + j];
                float d0 = (hq[2*i2]   + eq) - 2.0f*p.x;
                float d1 = (hq[2*i2+1] + eq) - 2.0f*p.y;
                if (d0 < best[2*i2])   { best[2*i2]   = d0; bidx[2*i2]   = cc; }
                if (d1 < best[2*i2+1]) { best[2*i2+1] = d1; bidx[2*i2+1] = cc; }
            }
        __syncthreads();
    }
    // reduce across the 8 tx lanes (tx = lane bits 0..2)
    #pragma unroll
    for (int i = 0; i < 4; i++) {
        float v = best[i]; int ix = bidx[i];
        #pragma unroll
        for (int off = 4; off; off >>= 1) {
            float ov = __shfl_xor_sync(0xFFFFFFFFu, v, off);
            int   oi = __shfl_xor_sync(0xFFFFFFFFu, ix, off);
            if (ov < v || (ov == v && oi < ix)) { v = ov; ix = oi; }
        }
        if (tx == 0) code[r0 + ty*4 + i] = ix;
    }
}

// ---------------- final output: gather embedInv rows (masked -> inv_b) ----------------
__global__ void k_output(const int* __restrict__ code, const int* __restrict__ mask,
                         const float* __restrict__ ei, const float* __restrict__ invb,
                         float* __restrict__ out) {
    int idx = blockIdx.x*256 + threadIdx.x;    // over BT*DD/4
    int r  = idx / 192;
    int c4 = idx - r*192;
    float4 v;
    if (mask[r]) v = ((const float4*)ei)[(size_t)code[r]*192 + c4];
    else         v = ((const float4*)invb)[c4];
    ((float4*)out)[idx] = v;
}
__global__ void k_codeout(const int* __restrict__ code, const int* __restrict__ mask,
                          float* __restrict__ code_out) {
    int r = blockIdx.x*256 + threadIdx.x;
    code_out[r] = (float)(mask[r] ? code[r] : 0);
}

// ---------------- launch ----------------
extern "C" void kernel_launch(void* const* d_in, const int* in_sizes, int n_in,
                              void* d_out, int out_size) {
    (void)in_sizes; (void)n_in;
    const float* h_in   = (const float*)d_in[0];
    const int*   mask   = (const int*)  d_in[1];
    const float* proj_w = (const float*)d_in[2];
    const float* proj_b = (const float*)d_in[3];
    const float* inv_w  = (const float*)d_in[4];
    const float* inv_b  = (const float*)d_in[5];
    const float* w_in   = (const float*)d_in[6];
    const float* b_in   = (const float*)d_in[7];
    const float* w_mid  = (const float*)d_in[8];
    const float* b_mid  = (const float*)d_in[9];
    const float* w_out  = (const float*)d_in[10];
    const float* b_out  = (const float*)d_in[11];
    const float* gamma  = (const float*)d_in[12];
    const float* beta   = (const float*)d_in[13];
    float* out = (float*)d_out;

    float *bufA, *bufB, *hT, *h, *hsq, *embed, *esq, *einv, *psum, *psumsq, *bns, *bnt;
    int* codep;
    cudaGetSymbolAddress((void**)&bufA,  g_bufA);
    cudaGetSymbolAddress((void**)&bufB,  g_bufB);
    cudaGetSymbolAddress((void**)&hT,    g_hT);
    cudaGetSymbolAddress((void**)&h,     g_h);
    cudaGetSymbolAddress((void**)&hsq,   g_hsq);
    cudaGetSymbolAddress((void**)&embed, g_embed);
    cudaGetSymbolAddress((void**)&esq,   g_esq);
    cudaGetSymbolAddress((void**)&einv,  g_einv);
    cudaGetSymbolAddress((void**)&psum,  g_psum);
    cudaGetSymbolAddress((void**)&psumsq,g_psumsq);
    cudaGetSymbolAddress((void**)&bns,   g_bns);
    cudaGetSymbolAddress((void**)&bnt,   g_bnt);
    cudaGetSymbolAddress((void**)&codep, g_code);

    const int ARG_SMEM = (64*132 + 64*68 + 64) * 4;   // 51456 B
    cudaFuncSetAttribute(k_argmin, cudaFuncAttributeMaxDynamicSharedMemorySize, ARG_SMEM);

    // ---- h path prep (independent): transpose h_in ----
    k_transpose<<<dim3(TT/32, DD/32, BB), dim3(32,8)>>>(h_in, hT);

    // ---- codebook MLP ----
    k_layer0<<<(KK*HID)/256, 256>>>(w_in, b_in, bufA);
    k_bn_part<<<dim3(HID/256, 32), 256>>>(bufA, psum, psumsq);
    k_bn_final<<<HID/256, 256>>>(psum, psumsq, gamma, beta, bns, bnt);
    for (int l = 0; l < NMID; l++) {
        float* Ain = (l & 1) ? bufB : bufA;
        float* Cot = (l & 1) ? bufA : bufB;
        k_gemm<128,128,16,8,8,true,true><<<dim3(HID/128, KK/128), 256>>>(
            Ain, bns, bnt, w_mid + (size_t)l*HID*HID, b_mid + l*HID,
            Cot, psum, psumsq, KK, HID, HID);
        k_bn_final<<<HID/256, 256>>>(psum, psumsq,
                                     gamma + (l+1)*HID, beta + (l+1)*HID, bns, bnt);
    }
    // out-linear with BN4 applied in prologue (Y4 in bufA) — retiled 64x64 for 64 CTAs
    k_gemm<64,64,16,4,4,true,false><<<dim3(VQn/64, KK/64), 256>>>(
        bufA, bns, bnt, w_out, b_out, embed, (float*)0, (float*)0, KK, VQn, HID);
    k_l2norm<<<KK/8, 256>>>(embed, esq, KK);

    // ---- embedInv = embedN @ inv_w^T + inv_b  [4096 x 768] ----
    k_gemm<128,128,16,8,8,false,false><<<dim3(DD/128, KK/128), 256>>>(
        embed, (float*)0, (float*)0, inv_w, inv_b, einv, (float*)0, (float*)0,
        KK, DD, VQn);

    // ---- h projection + normalize — retiled 64x64 for 256 CTAs ----
    k_gemm<64,64,16,4,4,false,false><<<dim3(VQn/64, BT/64), 256>>>(
        hT, (float*)0, (float*)0, proj_w, proj_b, h, (float*)0, (float*)0,
        BT, VQn, DD);
    k_l2norm<<<BT/8, 256>>>(h, hsq, BT);

    // ---- nearest code ----
    k_argmin<<<BT/128, 256, ARG_SMEM>>>(h, hsq, embed, esq, codep);

    // ---- output gather + codes ----
    k_output<<<(BT*DD/4)/256, 256>>>(codep, mask, einv, inv_b, out);
    if (out_size >= BT*DD + BT)
        k_codeout<<<BT/256, 256>>>(codep, mask, out + (size_t)BT*DD);
}

// round 11
// speedup vs baseline: 1.1311x; 1.1311x over previous
#include <cuda_runtime.h>
#include <math.h>

// ---------------- problem constants ----------------
#define BB   8
#define TT   2048
#define DD   768
#define VQn  64
#define KK   4096
#define HID  1024
#define NMID 4
#define BT   (BB*TT)          // 16384
#define EPS_N  1e-6f
#define EPS_BN 1e-5f
#define NSPLIT 4              // argmin code-dimension splits

typedef unsigned long long u64;

// ---------------- f32x2 packed-FMA primitives ----------------
__device__ __forceinline__ void ffma2(u64& d, u64 a, u64 b) {
    asm("fma.rn.f32x2 %0, %1, %2, %0;" : "+l"(d) : "l"(a), "l"(b));
}
__device__ __forceinline__ float2 u2f(u64 v) {
    float2 r; asm("mov.b64 {%0, %1}, %2;" : "=f"(r.x), "=f"(r.y) : "l"(v)); return r;
}
__device__ __forceinline__ u64 fdup(float x) {
    u64 r; asm("mov.b64 %0, {%1, %1};" : "=l"(r) : "f"(x)); return r;
}

// ---------------- device scratch ----------------
__device__ float g_bufA[KK*HID];        // 16 MB
__device__ float g_bufB[KK*HID];        // 16 MB
__device__ float g_hT[BT*DD];           // 50 MB   h_in transposed to [B,T,D]
__device__ float g_h[BT*VQn];           // 4 MB
__device__ float g_hsq[BT];
__device__ float g_embed[KK*VQn];
__device__ float g_esq[KK];
__device__ float g_einv[KK*DD];         // 12.6 MB
__device__ int   g_code[BT];
__device__ float g_psum[32*HID];
__device__ float g_psumsq[32*HID];
__device__ float g_bns[HID];
__device__ float g_bnt[HID];
__device__ float g_av[NSPLIT*BT];       // per-split best distance
__device__ int   g_ai[NSPLIT*BT];       // per-split best index

// ---------------- layer 0: bits @ W_in^T + b ----------------
__global__ void k_layer0(const float* __restrict__ w, const float* __restrict__ b,
                         float* __restrict__ Y) {
    int idx = blockIdx.x*256 + threadIdx.x;
    int k = idx >> 10, j = idx & 1023;
    float acc = 0.f;
    #pragma unroll
    for (int l = 0; l < 12; l++)
        if (k & (1 << (11-l))) acc += w[j*12 + l];
    Y[idx] = acc + b[j];
}

// ---------------- BN stats for layer0 output (deterministic 2-stage) ----------------
__global__ void k_bn_part(const float* __restrict__ Y,
                          float* __restrict__ ps, float* __restrict__ pss) {
    int j  = blockIdx.x*256 + threadIdx.x;
    int r0 = blockIdx.y * 128;
    float s = 0.f, ss = 0.f;
    for (int r = 0; r < 128; r++) {
        float v = Y[(r0+r)*HID + j];
        s += v; ss += v*v;
    }
    ps [blockIdx.y*HID + j] = s;
    pss[blockIdx.y*HID + j] = ss;
}
__global__ void k_bn_final(const float* __restrict__ ps, const float* __restrict__ pss,
                           const float* __restrict__ gamma, const float* __restrict__ beta,
                           float* __restrict__ so, float* __restrict__ to) {
    int j = blockIdx.x*256 + threadIdx.x;
    float s = 0.f, q = 0.f;
    #pragma unroll
    for (int p = 0; p < 32; p++) { s += ps[p*HID + j]; q += pss[p*HID + j]; }
    float m   = s * (1.0f/KK);
    float var = q * (1.0f/KK) - m*m;
    float inv = 1.0f / sqrtf(var + EPS_BN);
    float sc  = gamma[j] * inv;
    so[j] = sc;
    to[j] = beta[j] - m*sc;
}

// ---------------- fused NT SGEMM (FFMA2): C[M,N] = act(A)[M,K] * B[N,K]^T + bias ----------------
template<int BM,int BN,int BK,int TM,int TN,bool BNIN,bool STATS>
__global__ void __launch_bounds__(256, 2)
k_gemm(const float* __restrict__ A,
       const float* __restrict__ bns, const float* __restrict__ bnt,
       const float* __restrict__ B, const float* __restrict__ bias,
       float* __restrict__ C,
       float* __restrict__ ps, float* __restrict__ pss,
       int M, int N, int Kd) {
    constexpr int THREADS = (BM/TM)*(BN/TN);     // 256
    constexpr int ASTR = BM+4, BSTR = BN+4;
    constexpr int MAINF = BK*ASTR + BK*BSTR;
    constexpr int STATF = 2*(BM/TM)*BN;
    constexpr int SMEMF = (MAINF > STATF) ? MAINF : STATF;
    __shared__ float sm[SMEMF];
    float (*As)[ASTR] = (float(*)[ASTR])sm;
    float (*Bs)[BSTR] = (float(*)[BSTR])(sm + BK*ASTR);

    int tid = threadIdx.x;
    int tx = tid % (BN/TN);
    int ty = tid / (BN/TN);
    int m0 = blockIdx.y*BM, n0 = blockIdx.x*BN;

    u64 acc2[TM/2][TN];
    #pragma unroll
    for (int i = 0; i < TM/2; i++)
        #pragma unroll
        for (int j = 0; j < TN; j++) acc2[i][j] = 0ULL;

    constexpr int A_PER = (BM*BK/4)/THREADS;
    constexpr int B_PER = (BN*BK/4)/THREADS;

    for (int k0 = 0; k0 < Kd; k0 += BK) {
        #pragma unroll
        for (int i = 0; i < A_PER; i++) {
            int f = tid + i*THREADS;
            int m = f / (BK/4);
            int kc = (f % (BK/4)) * 4;
            float4 v = *(const float4*)&A[(size_t)(m0+m)*Kd + k0 + kc];
            if (BNIN) {
                float4 s4 = *(const float4*)&bns[k0 + kc];
                float4 t4 = *(const float4*)&bnt[k0 + kc];
                v.x = fmaxf(fmaf(v.x, s4.x, t4.x), 0.f);
                v.y = fmaxf(fmaf(v.y, s4.y, t4.y), 0.f);
                v.z = fmaxf(fmaf(v.z, s4.z, t4.z), 0.f);
                v.w = fmaxf(fmaf(v.w, s4.w, t4.w), 0.f);
            }
            As[kc+0][m]=v.x; As[kc+1][m]=v.y; As[kc+2][m]=v.z; As[kc+3][m]=v.w;
        }
        #pragma unroll
        for (int i = 0; i < B_PER; i++) {
            int f = tid + i*THREADS;
            int n = f / (BK/4);
            int kc = (f % (BK/4)) * 4;
            float4 v = *(const float4*)&B[(size_t)(n0+n)*Kd + k0 + kc];
            Bs[kc+0][n]=v.x; Bs[kc+1][n]=v.y; Bs[kc+2][n]=v.z; Bs[kc+3][n]=v.w;
        }
        __syncthreads();
        #pragma unroll
        for (int k = 0; k < BK; k++) {
            ulonglong2 av0 = *(const ulonglong2*)&As[k][ty*TM];
            ulonglong2 av1 = *(const ulonglong2*)&As[k][ty*TM + 4];
            u64 ap[4] = {av0.x, av0.y, av1.x, av1.y};
            u64 bd[TN];
            {
                float4 b0 = *(const float4*)&Bs[k][tx*TN];
                bd[0]=fdup(b0.x); bd[1]=fdup(b0.y); bd[2]=fdup(b0.z); bd[3]=fdup(b0.w);
                if (TN == 8) {
                    float4 b1 = *(const float4*)&Bs[k][tx*TN + 4];
                    bd[4]=fdup(b1.x); bd[5]=fdup(b1.y); bd[6]=fdup(b1.z); bd[7]=fdup(b1.w);
                }
            }
            #pragma unroll
            for (int i2 = 0; i2 < TM/2; i2++)
                #pragma unroll
                for (int j = 0; j < TN; j++)
                    ffma2(acc2[i2][j], ap[i2], bd[j]);
        }
        __syncthreads();
    }

    // epilogue: unpack + bias
    float accf[TM][TN];
    #pragma unroll
    for (int i2 = 0; i2 < TM/2; i2++)
        #pragma unroll
        for (int j = 0; j < TN; j++) {
            float2 p = u2f(acc2[i2][j]);
            float bj = bias[n0 + tx*TN + j];
            accf[2*i2][j]   = p.x + bj;
            accf[2*i2+1][j] = p.y + bj;
        }
    #pragma unroll
    for (int i = 0; i < TM; i++) {
        int m = m0 + ty*TM + i;
        #pragma unroll
        for (int jj = 0; jj < TN/4; jj++) {
            int n = n0 + tx*TN + jj*4;
            float4 v;
            v.x = accf[i][jj*4+0]; v.y = accf[i][jj*4+1];
            v.z = accf[i][jj*4+2]; v.w = accf[i][jj*4+3];
            *(float4*)&C[(size_t)m*N + n] = v;
        }
    }
    if (STATS) {
        __syncthreads();
        float* shS = sm;
        float* shQ = sm + (BM/TM)*BN;
        #pragma unroll
        for (int j = 0; j < TN; j++) {
            float s = 0.f, q = 0.f;
            #pragma unroll
            for (int i = 0; i < TM; i++) { float v = accf[i][j]; s += v; q += v*v; }
            shS[ty*BN + tx*TN + j] = s;
            shQ[ty*BN + tx*TN + j] = q;
        }
        __syncthreads();
        if (tid < BN) {
            float s = 0.f, q = 0.f;
            #pragma unroll
            for (int p = 0; p < BM/TM; p++) { s += shS[p*BN + tid]; q += shQ[p*BN + tid]; }
            ps [blockIdx.y*N + n0 + tid] = s;
            pss[blockIdx.y*N + n0 + tid] = q;
        }
    }
}

// ---------------- row L2-normalize (64-wide rows), post-norm sumsq ----------------
__global__ void k_l2norm(float* __restrict__ X, float* __restrict__ sq, int M) {
    int row  = blockIdx.x * 8 + (threadIdx.x >> 5);
    int lane = threadIdx.x & 31;
    if (row >= M) return;
    float* p = X + (size_t)row*64;
    float v0 = p[lane], v1 = p[lane+32];
    float s = v0*v0 + v1*v1;
    #pragma unroll
    for (int o = 16; o; o >>= 1) s += __shfl_xor_sync(0xFFFFFFFFu, s, o);
    float inv = 1.0f / (sqrtf(s) + EPS_N);
    v0 *= inv; v1 *= inv;
    p[lane] = v0; p[lane+32] = v1;
    float s2 = v0*v0 + v1*v1;
    #pragma unroll
    for (int o = 16; o; o >>= 1) s2 += __shfl_xor_sync(0xFFFFFFFFu, s2, o);
    if (lane == 0) sq[row] = s2;
}

// ---------------- transpose h_in [B,D,T] -> [B,T,D] ----------------
__global__ void k_transpose(const float* __restrict__ in, float* __restrict__ out) {
    __shared__ float tile[32][33];
    int b  = blockIdx.z;
    int t0 = blockIdx.x*32, d0 = blockIdx.y*32;
    int x = threadIdx.x, y = threadIdx.y;   // (32,8)
    #pragma unroll
    for (int i = 0; i < 32; i += 8)
        tile[y+i][x] = in[(size_t)b*DD*TT + (size_t)(d0+y+i)*TT + t0 + x];
    __syncthreads();
    #pragma unroll
    for (int i = 0; i < 32; i += 8)
        out[(size_t)b*TT*DD + (size_t)(t0+y+i)*DD + d0 + x] = tile[x][y+i];
}

// ---------------- fused distance + argmin, split over code dim ----------------
// blockIdx.x: row group (128 rows); blockIdx.y: code split (1024 codes).
// Per-(row,code) distance is bit-identical to the unsplit version (self-contained
// 64-wide k accumulation); split results merged with global first-index-min.
__global__ void __launch_bounds__(128)
k_argmin(const float* __restrict__ h, const float* __restrict__ hsq,
         const float* __restrict__ embed, const float* __restrict__ esq,
         float* __restrict__ av, int* __restrict__ ai) {
    extern __shared__ float dsm[];
    float (*Hst)[132] = (float(*)[132])dsm;            // [64 k][128 rows + pad]
    float (*Est)[68]  = (float(*)[68])(dsm + 64*132);  // [64 k][64 codes + pad]
    float* Eq = dsm + 64*132 + 64*68;                  // [64]
    int tid = threadIdx.x;
    int tx = tid & 7;          // code group (8)
    int ty = tid >> 3;         // row group (16)
    int r0 = blockIdx.x * 128;
    int cbase = blockIdx.y * (KK/NSPLIT);

    // load H tile [128 rows][64 k]
    #pragma unroll
    for (int i = 0; i < 16; i++) {
        int f = tid + i*128;
        int r = f >> 4;
        int kc = (f & 15) * 4;
        float4 v = *(const float4*)&h[(size_t)(r0+r)*64 + kc];
        Hst[kc+0][r]=v.x; Hst[kc+1][r]=v.y; Hst[kc+2][r]=v.z; Hst[kc+3][r]=v.w;
    }
    float hq[8];
    #pragma unroll
    for (int i = 0; i < 8; i++) hq[i] = hsq[r0 + ty*8 + i];
    float best[8]; int bidx[8];
    #pragma unroll
    for (int i = 0; i < 8; i++) { best[i] = 3.4e38f; bidx[i] = 0; }

    for (int cc0 = 0; cc0 < KK/NSPLIT; cc0 += 64) {
        int c0 = cbase + cc0;
        #pragma unroll
        for (int i = 0; i < 8; i++) {
            int f = tid + i*128;
            int c = f >> 4;
            int kc = (f & 15) * 4;
            float4 v = *(const float4*)&embed[(size_t)(c0+c)*64 + kc];
            Est[kc+0][c]=v.x; Est[kc+1][c]=v.y; Est[kc+2][c]=v.z; Est[kc+3][c]=v.w;
        }
        if (tid < 64) Eq[tid] = esq[c0 + tid];
        __syncthreads();
        u64 acc2[4][8];
        #pragma unroll
        for (int i = 0; i < 4; i++)
            #pragma unroll
            for (int j = 0; j < 8; j++) acc2[i][j] = 0ULL;
        #pragma unroll 16
        for (int k = 0; k < 64; k++) {
            ulonglong2 a0 = *(const ulonglong2*)&Hst[k][ty*8];
            ulonglong2 a1 = *(const ulonglong2*)&Hst[k][ty*8 + 4];
            u64 ap[4] = {a0.x, a0.y, a1.x, a1.y};
            float4 b0 = *(const float4*)&Est[k][tx*8];
            float4 b1 = *(const float4*)&Est[k][tx*8 + 4];
            u64 bd[8] = {fdup(b0.x), fdup(b0.y), fdup(b0.z), fdup(b0.w),
                         fdup(b1.x), fdup(b1.y), fdup(b1.z), fdup(b1.w)};
            #pragma unroll
            for (int i2 = 0; i2 < 4; i2++)
                #pragma unroll
                for (int j = 0; j < 8; j++)
                    ffma2(acc2[i2][j], ap[i2], bd[j]);
        }
        #pragma unroll
        for (int i2 = 0; i2 < 4; i2++)
            #pragma unroll
            for (int j = 0; j < 8; j++) {
                float2 p = u2f(acc2[i2][j]);
                int cc = c0 + tx*8 + j;
                float eq = Eq[tx*8 + j];
                float d0 = (hq[2*i2]   + eq) - 2.0f*p.x;
                float d1 = (hq[2*i2+1] + eq) - 2.0f*p.y;
                if (d0 < best[2*i2])   { best[2*i2]   = d0; bidx[2*i2]   = cc; }
                if (d1 < best[2*i2+1]) { best[2*i2+1] = d1; bidx[2*i2+1] = cc; }
            }
        __syncthreads();
    }
    // reduce across the 8 tx lanes (aligned 8-lane groups within each warp)
    #pragma unroll
    for (int i = 0; i < 8; i++) {
        float v = best[i]; int ix = bidx[i];
        #pragma unroll
        for (int off = 4; off; off >>= 1) {
            float ov = __shfl_xor_sync(0xFFFFFFFFu, v, off);
            int   oi = __shfl_xor_sync(0xFFFFFFFFu, ix, off);
            if (ov < v || (ov == v && oi < ix)) { v = ov; ix = oi; }
        }
        if (tx == 0) {
            int r = r0 + ty*8 + i;
            av[blockIdx.y*BT + r] = v;
            ai[blockIdx.y*BT + r] = ix;
        }
    }
}

// merge splits (split s covers codes [s*K/NSPLIT, ...), ordered -> first-index min)
__global__ void k_argmerge(const float* __restrict__ av, const int* __restrict__ ai,
                           int* __restrict__ code) {
    int r = blockIdx.x*256 + threadIdx.x;
    float bv = av[r]; int bi = ai[r];
    #pragma unroll
    for (int s = 1; s < NSPLIT; s++) {
        float v = av[s*BT + r]; int ix = ai[s*BT + r];
        if (v < bv || (v == bv && ix < bi)) { bv = v; bi = ix; }
    }
    code[r] = bi;
}

// ---------------- final output: gather embedInv rows (masked -> inv_b) ----------------
__global__ void k_output(const int* __restrict__ code, const int* __restrict__ mask,
                         const float* __restrict__ ei, const float* __restrict__ invb,
                         float* __restrict__ out) {
    int idx = blockIdx.x*256 + threadIdx.x;    // over BT*DD/4
    int r  = idx / 192;
    int c4 = idx - r*192;
    float4 v;
    if (mask[r]) v = ((const float4*)ei)[(size_t)code[r]*192 + c4];
    else         v = ((const float4*)invb)[c4];
    ((float4*)out)[idx] = v;
}
__global__ void k_codeout(const int* __restrict__ code, const int* __restrict__ mask,
                          float* __restrict__ code_out) {
    int r = blockIdx.x*256 + threadIdx.x;
    code_out[r] = (float)(mask[r] ? code[r] : 0);
}

// ---------------- launch ----------------
extern "C" void kernel_launch(void* const* d_in, const int* in_sizes, int n_in,
                              void* d_out, int out_size) {
    (void)in_sizes; (void)n_in;
    const float* h_in   = (const float*)d_in[0];
    const int*   mask   = (const int*)  d_in[1];
    const float* proj_w = (const float*)d_in[2];
    const float* proj_b = (const float*)d_in[3];
    const float* inv_w  = (const float*)d_in[4];
    const float* inv_b  = (const float*)d_in[5];
    const float* w_in   = (const float*)d_in[6];
    const float* b_in   = (const float*)d_in[7];
    const float* w_mid  = (const float*)d_in[8];
    const float* b_mid  = (const float*)d_in[9];
    const float* w_out  = (const float*)d_in[10];
    const float* b_out  = (const float*)d_in[11];
    const float* gamma  = (const float*)d_in[12];
    const float* beta   = (const float*)d_in[13];
    float* out = (float*)d_out;

    float *bufA, *bufB, *hT, *h, *hsq, *embed, *esq, *einv, *psum, *psumsq, *bns, *bnt;
    float *avp; int *aip, *codep;
    cudaGetSymbolAddress((void**)&bufA,  g_bufA);
    cudaGetSymbolAddress((void**)&bufB,  g_bufB);
    cudaGetSymbolAddress((void**)&hT,    g_hT);
    cudaGetSymbolAddress((void**)&h,     g_h);
    cudaGetSymbolAddress((void**)&hsq,   g_hsq);
    cudaGetSymbolAddress((void**)&embed, g_embed);
    cudaGetSymbolAddress((void**)&esq,   g_esq);
    cudaGetSymbolAddress((void**)&einv,  g_einv);
    cudaGetSymbolAddress((void**)&psum,  g_psum);
    cudaGetSymbolAddress((void**)&psumsq,g_psumsq);
    cudaGetSymbolAddress((void**)&bns,   g_bns);
    cudaGetSymbolAddress((void**)&bnt,   g_bnt);
    cudaGetSymbolAddress((void**)&codep, g_code);
    cudaGetSymbolAddress((void**)&avp,   g_av);
    cudaGetSymbolAddress((void**)&aip,   g_ai);

    const int ARG_SMEM = (64*132 + 64*68 + 64) * 4;   // 51456 B
    cudaFuncSetAttribute(k_argmin, cudaFuncAttributeMaxDynamicSharedMemorySize, ARG_SMEM);

    // ---- codebook MLP (launched first so ncu -s 5 lands on mid-GEMM l=1) ----
    k_layer0<<<(KK*HID)/256, 256>>>(w_in, b_in, bufA);
    k_bn_part<<<dim3(HID/256, 32), 256>>>(bufA, psum, psumsq);
    k_bn_final<<<HID/256, 256>>>(psum, psumsq, gamma, beta, bns, bnt);
    for (int l = 0; l < NMID; l++) {
        float* Ain = (l & 1) ? bufB : bufA;
        float* Cot = (l & 1) ? bufA : bufB;
        k_gemm<128,128,32,8,8,true,true><<<dim3(HID/128, KK/128), 256>>>(
            Ain, bns, bnt, w_mid + (size_t)l*HID*HID, b_mid + l*HID,
            Cot, psum, psumsq, KK, HID, HID);
        k_bn_final<<<HID/256, 256>>>(psum, psumsq,
                                     gamma + (l+1)*HID, beta + (l+1)*HID, bns, bnt);
    }
    // out-linear with BN4 applied in prologue (Y4 in bufA)
    k_gemm<128,64,16,8,4,true,false><<<dim3(1, KK/128), 256>>>(
        bufA, bns, bnt, w_out, b_out, embed, (float*)0, (float*)0, KK, VQn, HID);
    k_l2norm<<<KK/8, 256>>>(embed, esq, KK);

    // ---- embedInv = embedN @ inv_w^T + inv_b  [4096 x 768] ----
    k_gemm<128,128,16,8,8,false,false><<<dim3(DD/128, KK/128), 256>>>(
        embed, (float*)0, (float*)0, inv_w, inv_b, einv, (float*)0, (float*)0,
        KK, DD, VQn);

    // ---- h path: transpose then projection + normalize ----
    k_transpose<<<dim3(TT/32, DD/32, BB), dim3(32,8)>>>(h_in, hT);
    k_gemm<128,64,16,8,4,false,false><<<dim3(1, BT/128), 256>>>(
        hT, (float*)0, (float*)0, proj_w, proj_b, h, (float*)0, (float*)0,
        BT, VQn, DD);
    k_l2norm<<<BT/8, 256>>>(h, hsq, BT);

    // ---- nearest code: split over codes, then merge ----
    k_argmin<<<dim3(BT/128, NSPLIT), 128, ARG_SMEM>>>(h, hsq, embed, esq, avp, aip);
    k_argmerge<<<BT/256, 256>>>(avp, aip, codep);

    // ---- output gather + codes ----
    k_output<<<(BT*DD/4)/256, 256>>>(codep, mask, einv, inv_b, out);
    if (out_size >= BT*DD + BT)
        k_codeout<<<BT/256, 256>>>(codep, mask, out + (size_t)BT*DD);
}